// round 4
// baseline (speedup 1.0000x reference)
#include <cuda_runtime.h>
#include <cstdint>

// MaskedDenseLayer: BS=256, K=1024, N=1024, NUM_STATES=20
#define BSZ      256
#define KDIM     1024
#define NDIM     1024
#define NSTATES  20

#define KSPLIT   8
#define TKB      (KDIM / KSPLIT)   // 128 k-rows per block
#define TNB      256               // 256 cols per block (128 threads x 2 cols)
#define NTHREADS 128
#define NTILES   (NDIM / TNB)      // 4
#define RGP      36                // smem row stride (144B, 16B-aligned)

// Static scratch (allocation-free rules)
__device__ float    g_partial[(size_t)KSPLIT * BSZ * NDIM];    // 8 MB
__device__ unsigned g_arrive[NTILES * NSTATES];                // zero-init, self-resetting

// ---------------------------------------------------------------------------
// Packed f32x2 helpers (Blackwell FFMA2 — PTX-only path)
// ---------------------------------------------------------------------------
__device__ __forceinline__ unsigned long long u64_pack(unsigned a, unsigned b) {
    unsigned long long r;
    asm("mov.b64 %0, {%1,%2};" : "=l"(r) : "r"(a), "r"(b));
    return r;
}
__device__ __forceinline__ void u64_unpack(unsigned long long v, unsigned& a, unsigned& b) {
    asm("mov.b64 {%0,%1}, %2;" : "=r"(a), "=r"(b) : "l"(v));
}
__device__ __forceinline__ unsigned long long mul_f32x2(unsigned long long a, unsigned long long b) {
    unsigned long long r;
    asm("mul.rn.f32x2 %0, %1, %2;" : "=l"(r) : "l"(a), "l"(b));
    return r;
}
__device__ __forceinline__ unsigned long long fma_f32x2(unsigned long long a, unsigned long long b,
                                                        unsigned long long c) {
    unsigned long long r;
    asm("fma.rn.f32x2 %0, %1, %2, %3;" : "=l"(r) : "l"(a), "l"(b), "l"(c));
    return r;
}

// ---------------------------------------------------------------------------
// One row-group of R (padded) rows: stage x transposed, masked-GEMM over the
// block's 128-k x 256-n tile (k/m loads software-pipelined), scatter split-K
// partials.
// ---------------------------------------------------------------------------
template<int R>
__device__ __forceinline__ void group_body(
    int rg, int ms, int tid, int kb,
    const float* __restrict__ x,
    const float* __restrict__ kbase,
    const float* __restrict__ mbase,
    const int*   srows,
    float (&xs)[TKB][RGP],
    float* __restrict__ pbase)
{
    // ---- stage x rows (transposed), zero-pad to R ----
    #pragma unroll 1
    for (int r = 0; r < R; ++r) {
        float v = 0.f;
        int idx = rg + r;
        if (idx < ms) v = x[(size_t)srows[idx] * KDIM + kb + tid];
        xs[tid][r] = v;
    }
    __syncthreads();

    unsigned long long accA[R / 2];   // col n0,   row pairs packed
    unsigned long long accB[R / 2];   // col n0+1
    #pragma unroll
    for (int j = 0; j < R / 2; ++j) { accA[j] = 0ULL; accB[j] = 0ULL; }

    // ---- software-pipelined k/m loads: prefetch kk+1 while computing kk ----
    float2 k_cur = *reinterpret_cast<const float2*>(kbase);
    float2 m_cur = *reinterpret_cast<const float2*>(mbase);

    #pragma unroll 2
    for (int kk = 0; kk < TKB; ++kk) {
        float2 k_nxt, m_nxt;
        if (kk + 1 < TKB) {
            k_nxt = *reinterpret_cast<const float2*>(kbase + (size_t)(kk + 1) * NDIM);
            m_nxt = *reinterpret_cast<const float2*>(mbase + (size_t)(kk + 1) * NDIM);
        }

        unsigned long long wm = mul_f32x2(
            u64_pack(__float_as_uint(k_cur.x), __float_as_uint(k_cur.y)),
            u64_pack(__float_as_uint(m_cur.x), __float_as_uint(m_cur.y)));
        unsigned lo, hi;
        u64_unpack(wm, lo, hi);
        const unsigned long long wA = u64_pack(lo, lo);
        const unsigned long long wB = u64_pack(hi, hi);

        const ulonglong2* xp = reinterpret_cast<const ulonglong2*>(&xs[kk][0]);
        #pragma unroll
        for (int j4 = 0; j4 < R / 4; ++j4) {
            ulonglong2 xv = xp[j4];             // LDS.128 broadcast (all lanes same addr)
            accA[2 * j4]     = fma_f32x2(xv.x, wA, accA[2 * j4]);
            accB[2 * j4]     = fma_f32x2(xv.x, wB, accB[2 * j4]);
            accA[2 * j4 + 1] = fma_f32x2(xv.y, wA, accA[2 * j4 + 1]);
            accB[2 * j4 + 1] = fma_f32x2(xv.y, wB, accB[2 * j4 + 1]);
        }

        k_cur = k_nxt;
        m_cur = m_nxt;
    }

    // ---- scatter partials: g_partial[kz][row][n0..n0+1] ----
    #pragma unroll
    for (int j = 0; j < R / 2; ++j) {
        unsigned a0, a1, b0, b1;
        u64_unpack(accA[j], a0, a1);
        u64_unpack(accB[j], b0, b1);
        int r0 = rg + 2 * j, r1 = r0 + 1;
        if (r0 < ms) {
            float2 v = make_float2(__uint_as_float(a0), __uint_as_float(b0));
            *reinterpret_cast<float2*>(pbase + (size_t)srows[r0] * NDIM) = v;
        }
        if (r1 < ms) {
            float2 v = make_float2(__uint_as_float(a1), __uint_as_float(b1));
            *reinterpret_cast<float2*>(pbase + (size_t)srows[r1] * NDIM) = v;
        }
    }
    __syncthreads();   // xs reuse safety if multiple groups
}

// ---------------------------------------------------------------------------
// Fused kernel: build row list + grouped masked GEMM + last-block split-K
// reduce + ReLU. grid = (NTILES, NSTATES, KSPLIT), 128 threads.
// ---------------------------------------------------------------------------
__global__ void __launch_bounds__(NTHREADS, 4) mdl_fused(
    const float* __restrict__ x,
    const int*   __restrict__ state,
    const float* __restrict__ kern,
    const float* __restrict__ masks,
    float*       __restrict__ out)
{
    const int s     = blockIdx.y;
    const int ntile = blockIdx.x;
    const int kz    = blockIdx.z;
    const int tid   = threadIdx.x;

    __shared__ int srows[BSZ];
    __shared__ int scnt;
    __shared__ int s_last;
    __shared__ __align__(16) float xs[TKB][RGP];   // 18.4 KB

    // ---- build row list for this state (redundant per block, cheap) ----
    if (tid == 0) scnt = 0;
    __syncthreads();
    for (int t = tid; t < BSZ; t += NTHREADS) {
        if (state[t] == s) {
            int p = atomicAdd(&scnt, 1);
            srows[p] = t;
        }
    }
    __syncthreads();
    const int ms = scnt;
    if (ms == 0) return;   // no rows -> no outputs for this state anywhere

    const int kb = kz * TKB;
    const int n0 = ntile * TNB + 2 * tid;
    const float* kbase = kern  + (size_t)kb * NDIM + n0;
    const float* mbase = masks + ((size_t)s * KDIM + kb) * NDIM + n0;
    float*       pbase = g_partial + (size_t)kz * BSZ * NDIM + n0;

    // ---- one-pass row groups, padded to next multiple of 8 ----
    int rg = 0;
    while (rg < ms) {
        int left = ms - rg;
        if      (left <= 8)  { group_body<8 >(rg, ms, tid, kb, x, kbase, mbase, srows, xs, pbase); rg += 8;  }
        else if (left <= 16) { group_body<16>(rg, ms, tid, kb, x, kbase, mbase, srows, xs, pbase); rg += 16; }
        else if (left <= 24) { group_body<24>(rg, ms, tid, kb, x, kbase, mbase, srows, xs, pbase); rg += 24; }
        else                 { group_body<32>(rg, ms, tid, kb, x, kbase, mbase, srows, xs, pbase); rg += 32; }
    }

    // ---- split-K completion handshake (threadFenceReduction pattern) ----
    __threadfence();
    __syncthreads();
    const int region = ntile * NSTATES + s;
    if (tid == 0) {
        unsigned old = atomicAdd(&g_arrive[region], 1u);
        s_last = (old == KSPLIT - 1);
        if (s_last) g_arrive[region] = 0;   // reset for next graph replay
    }
    __syncthreads();
    if (!s_last) return;
    __threadfence();   // acquire side: order partial reads after the arrival observation

    // ---- last block per region: reduce KSPLIT partials + ReLU ----
    for (int r = 0; r < ms; ++r) {
        const int row = srows[r];
        const float* pr = g_partial + (size_t)row * NDIM + n0;
        float2 acc = *reinterpret_cast<const float2*>(pr);
        #pragma unroll
        for (int z = 1; z < KSPLIT; ++z) {
            float2 b = *reinterpret_cast<const float2*>(pr + (size_t)z * BSZ * NDIM);
            acc.x += b.x; acc.y += b.y;
        }
        acc.x = fmaxf(acc.x, 0.f);
        acc.y = fmaxf(acc.y, 0.f);
        *reinterpret_cast<float2*>(out + (size_t)row * NDIM + n0) = acc;
    }
}

// ---------------------------------------------------------------------------
extern "C" void kernel_launch(void* const* d_in, const int* in_sizes, int n_in,
                              void* d_out, int out_size)
{
    const float* x     = nullptr;
    const int*   state = nullptr;
    const float* kern  = nullptr;
    const float* masks = nullptr;
    for (int i = 0; i < n_in; ++i) {
        switch (in_sizes[i]) {
            case BSZ * KDIM:            x     = (const float*)d_in[i]; break;
            case BSZ:                   state = (const int*)  d_in[i]; break;
            case KDIM * NDIM:           kern  = (const float*)d_in[i]; break;
            case NSTATES * KDIM * NDIM: masks = (const float*)d_in[i]; break;
            default: break;
        }
    }
    float* out = (float*)d_out;

    dim3 grid(NTILES, NSTATES, KSPLIT);
    mdl_fused<<<grid, NTHREADS>>>(x, state, kern, masks, out);
}

// round 7
// speedup vs baseline: 1.1970x; 1.1970x over previous
#include <cuda_runtime.h>
#include <cstdint>

// MaskedDenseLayer: BS=256, K=1024, N=1024, NUM_STATES=20
#define BSZ      256
#define KDIM     1024
#define NDIM     1024
#define NSTATES  20

#define KSPLIT   16
#define TKB      (KDIM / KSPLIT)   // 64 k-rows per block
#define TNB      256               // 256 cols per block (128 threads x 2 cols)
#define NTHREADS 128
#define NTILES   (NDIM / TNB)      // 4
#define RCHUNKS  2                 // row-chunk blocks per (ntile,state,kz)
#define ARRIVALS (KSPLIT * RCHUNKS)
#define RGP      20                // smem row stride (80B, 16B-aligned)
#define RMAX     16

// Static scratch (allocation-free rules)
__device__ float    g_partial[(size_t)KSPLIT * BSZ * NDIM];    // 16 MB
__device__ unsigned g_arrive[NTILES * NSTATES];                // zero-init, self-resetting

// ---------------------------------------------------------------------------
// Packed f32x2 helpers (Blackwell FFMA2 — PTX-only path)
// ---------------------------------------------------------------------------
__device__ __forceinline__ unsigned long long u64_pack(unsigned a, unsigned b) {
    unsigned long long r;
    asm("mov.b64 %0, {%1,%2};" : "=l"(r) : "r"(a), "r"(b));
    return r;
}
__device__ __forceinline__ void u64_unpack(unsigned long long v, unsigned& a, unsigned& b) {
    asm("mov.b64 {%0,%1}, %2;" : "=r"(a), "=r"(b) : "l"(v));
}
__device__ __forceinline__ unsigned long long mul_f32x2(unsigned long long a, unsigned long long b) {
    unsigned long long r;
    asm("mul.rn.f32x2 %0, %1, %2;" : "=l"(r) : "l"(a), "l"(b));
    return r;
}
__device__ __forceinline__ unsigned long long fma_f32x2(unsigned long long a, unsigned long long b,
                                                        unsigned long long c) {
    unsigned long long r;
    asm("fma.rn.f32x2 %0, %1, %2, %3;" : "=l"(r) : "l"(a), "l"(b), "l"(c));
    return r;
}

// ---------------------------------------------------------------------------
// One row-group of <=R rows [rg, rend): stage x transposed, masked-GEMM over
// the block's 64-k x 256-n tile (distance-2 prefetch, 2 kk per iter), scatter
// split-K partials.
// ---------------------------------------------------------------------------
template<int R>
__device__ __forceinline__ void group_body(
    int rg, int rend, int tid, int kb,
    const float* __restrict__ x,
    const float* __restrict__ kbase,
    const float* __restrict__ mbase,
    const int*   srows,
    float (&xs)[TKB][RGP],
    float* __restrict__ pbase)
{
    // ---- stage x rows (transposed), zero-pad to R ----
    #pragma unroll 1
    for (int idx = tid; idx < TKB * R; idx += NTHREADS) {
        int r  = idx / TKB;
        int kk = idx % TKB;
        float v = 0.f;
        if (rg + r < rend) v = x[(size_t)srows[rg + r] * KDIM + kb + kk];
        xs[kk][r] = v;
    }
    __syncthreads();

    unsigned long long accA[R / 2];   // col n0,   row pairs packed
    unsigned long long accB[R / 2];   // col n0+1
    #pragma unroll
    for (int j = 0; j < R / 2; ++j) { accA[j] = 0ULL; accB[j] = 0ULL; }

    // ---- distance-2 prefetched k/m loads, 2 kk per iteration (MLP=4) ----
    float2 k0 = *reinterpret_cast<const float2*>(kbase);
    float2 m0 = *reinterpret_cast<const float2*>(mbase);
    float2 k1 = *reinterpret_cast<const float2*>(kbase + NDIM);
    float2 m1 = *reinterpret_cast<const float2*>(mbase + NDIM);

    #pragma unroll 1
    for (int kk = 0; kk < TKB; kk += 2) {
        float2 k2v, m2v, k3v, m3v;
        if (kk + 2 < TKB) {
            k2v = *reinterpret_cast<const float2*>(kbase + (size_t)(kk + 2) * NDIM);
            m2v = *reinterpret_cast<const float2*>(mbase + (size_t)(kk + 2) * NDIM);
            k3v = *reinterpret_cast<const float2*>(kbase + (size_t)(kk + 3) * NDIM);
            m3v = *reinterpret_cast<const float2*>(mbase + (size_t)(kk + 3) * NDIM);
        }

        #pragma unroll
        for (int u = 0; u < 2; ++u) {
            const float2 kv = (u == 0) ? k0 : k1;
            const float2 mv = (u == 0) ? m0 : m1;
            unsigned long long wm = mul_f32x2(
                u64_pack(__float_as_uint(kv.x), __float_as_uint(kv.y)),
                u64_pack(__float_as_uint(mv.x), __float_as_uint(mv.y)));
            unsigned lo, hi;
            u64_unpack(wm, lo, hi);
            const unsigned long long wA = u64_pack(lo, lo);
            const unsigned long long wB = u64_pack(hi, hi);

            const ulonglong2* xp = reinterpret_cast<const ulonglong2*>(&xs[kk + u][0]);
            #pragma unroll
            for (int j4 = 0; j4 < R / 4; ++j4) {
                ulonglong2 xv = xp[j4];             // LDS.128 broadcast
                accA[2 * j4]     = fma_f32x2(xv.x, wA, accA[2 * j4]);
                accB[2 * j4]     = fma_f32x2(xv.x, wB, accB[2 * j4]);
                accA[2 * j4 + 1] = fma_f32x2(xv.y, wA, accA[2 * j4 + 1]);
                accB[2 * j4 + 1] = fma_f32x2(xv.y, wB, accB[2 * j4 + 1]);
            }
        }

        k0 = k2v; m0 = m2v; k1 = k3v; m1 = m3v;
    }

    // ---- scatter partials: g_partial[kz][row][n0..n0+1] ----
    #pragma unroll
    for (int j = 0; j < R / 2; ++j) {
        unsigned a0, a1, b0, b1;
        u64_unpack(accA[j], a0, a1);
        u64_unpack(accB[j], b0, b1);
        int r0 = rg + 2 * j, r1 = r0 + 1;
        if (r0 < rend) {
            float2 v = make_float2(__uint_as_float(a0), __uint_as_float(b0));
            *reinterpret_cast<float2*>(pbase + (size_t)srows[r0] * NDIM) = v;
        }
        if (r1 < rend) {
            float2 v = make_float2(__uint_as_float(a1), __uint_as_float(b1));
            *reinterpret_cast<float2*>(pbase + (size_t)srows[r1] * NDIM) = v;
        }
    }
    __syncthreads();   // xs reuse safety if chunk needs >1 group (ms>32 only)
}

// ---------------------------------------------------------------------------
// Fused kernel. grid = (NTILES, NSTATES, KSPLIT*RCHUNKS), 128 threads.
// blockIdx.z -> (kz = z/RCHUNKS, rc = z%RCHUNKS). Row chunks are split evenly
// across rc so every block does a single <=16-row pass in the common case.
// ---------------------------------------------------------------------------
__global__ void __launch_bounds__(NTHREADS, 5) mdl_fused(
    const float* __restrict__ x,
    const int*   __restrict__ state,
    const float* __restrict__ kern,
    const float* __restrict__ masks,
    float*       __restrict__ out)
{
    const int s     = blockIdx.y;
    const int ntile = blockIdx.x;
    const int kz    = blockIdx.z / RCHUNKS;
    const int rc    = blockIdx.z % RCHUNKS;
    const int tid   = threadIdx.x;

    __shared__ int srows[BSZ];
    __shared__ int warp_cnt[8];
    __shared__ int s_ms;       // total rows for this state (separate from warp_cnt!)
    __shared__ int s_last;
    __shared__ __align__(16) float xs[TKB][RGP];   // 5 KB

    // ---- deterministic (ascending) row list via warp ballots ----
    {
        const int lane = tid & 31;
        const int w    = tid >> 5;                  // 4 warps
        const int r0   = w * 32 + lane;             // rows 0..127
        const int r1   = 128 + w * 32 + lane;       // rows 128..255
        const bool m0 = (state[r0] == s);
        const bool m1 = (state[r1] == s);
        const unsigned b0 = __ballot_sync(0xffffffffu, m0);
        const unsigned b1 = __ballot_sync(0xffffffffu, m1);
        if (lane == 0) { warp_cnt[w] = __popc(b0); warp_cnt[4 + w] = __popc(b1); }
        __syncthreads();
        int preA = 0, preB = 0, tot = 0;
        #pragma unroll
        for (int i = 0; i < 8; ++i) {
            int c = warp_cnt[i];
            if (i < w)              preA += c;
            if (i < 4 || i < 4 + w) preB += c;
            tot += c;
        }
        const unsigned ltmask = (1u << lane) - 1u;
        if (m0) srows[preA + __popc(b0 & ltmask)] = r0;
        if (m1) srows[preB + __popc(b1 & ltmask)] = r1;
        if (tid == 0) s_ms = tot;                  // distinct variable: no race
        __syncthreads();
    }
    const int ms = s_ms;
    if (ms == 0) return;   // state absent -> no outputs, no arrivals needed

    // ---- this block's row chunk (deterministic, even split) ----
    int cs, ce;
    if (ms <= RMAX) { cs = (rc == 0) ? 0 : ms; ce = ms; }       // chunk1 empty
    else {
        int csz = (ms + RCHUNKS - 1) / RCHUNKS;
        cs = rc * csz; if (cs > ms) cs = ms;
        ce = cs + csz; if (ce > ms) ce = ms;
    }

    const int kb = kz * TKB;
    const int n0 = ntile * TNB + 2 * tid;
    const float* kbase = kern  + (size_t)kb * NDIM + n0;
    const float* mbase = masks + ((size_t)s * KDIM + kb) * NDIM + n0;
    float*       pbase = g_partial + (size_t)kz * BSZ * NDIM + n0;

    // ---- single padded pass (loop only if chunk > 16, i.e. ms > 32) ----
    while (cs < ce) {
        int left = ce - cs;
        if      (left <= 4)  { group_body<4 >(cs, ce, tid, kb, x, kbase, mbase, srows, xs, pbase); cs += 4;  }
        else if (left <= 8)  { group_body<8 >(cs, ce, tid, kb, x, kbase, mbase, srows, xs, pbase); cs += 8;  }
        else if (left <= 12) { group_body<12>(cs, ce, tid, kb, x, kbase, mbase, srows, xs, pbase); cs += 12; }
        else                 { group_body<16>(cs, ce, tid, kb, x, kbase, mbase, srows, xs, pbase); cs += 16; }
    }

    // ---- split-K completion handshake (threadFenceReduction pattern) ----
    __threadfence();
    __syncthreads();
    const int region = ntile * NSTATES + s;
    if (tid == 0) {
        unsigned old = atomicAdd(&g_arrive[region], 1u);
        s_last = (old == ARRIVALS - 1);
        if (s_last) g_arrive[region] = 0;   // reset for next graph replay
    }
    __syncthreads();
    if (!s_last) return;
    __threadfence();   // acquire side

    // ---- last block per region: reduce KSPLIT partials + ReLU ----
    for (int r = 0; r < ms; ++r) {
        const int row = srows[r];
        const float* pr = g_partial + (size_t)row * NDIM + n0;
        float2 acc = *reinterpret_cast<const float2*>(pr);
        #pragma unroll
        for (int z = 1; z < KSPLIT; ++z) {
            float2 b = *reinterpret_cast<const float2*>(pr + (size_t)z * BSZ * NDIM);
            acc.x += b.x; acc.y += b.y;
        }
        acc.x = fmaxf(acc.x, 0.f);
        acc.y = fmaxf(acc.y, 0.f);
        *reinterpret_cast<float2*>(out + (size_t)row * NDIM + n0) = acc;
    }
}

// ---------------------------------------------------------------------------
extern "C" void kernel_launch(void* const* d_in, const int* in_sizes, int n_in,
                              void* d_out, int out_size)
{
    const float* x     = nullptr;
    const int*   state = nullptr;
    const float* kern  = nullptr;
    const float* masks = nullptr;
    for (int i = 0; i < n_in; ++i) {
        switch (in_sizes[i]) {
            case BSZ * KDIM:            x     = (const float*)d_in[i]; break;
            case BSZ:                   state = (const int*)  d_in[i]; break;
            case KDIM * NDIM:           kern  = (const float*)d_in[i]; break;
            case NSTATES * KDIM * NDIM: masks = (const float*)d_in[i]; break;
            default: break;
        }
    }
    float* out = (float*)d_out;

    dim3 grid(NTILES, NSTATES, KSPLIT * RCHUNKS);
    mdl_fused<<<grid, NTHREADS>>>(x, state, kern, masks, out);
}

// round 11
// speedup vs baseline: 1.2687x; 1.0599x over previous
#include <cuda_runtime.h>
#include <cstdint>

// MaskedDenseLayer: BS=256, K=1024, N=1024, NUM_STATES=20
#define BSZ      256
#define KDIM     1024
#define NDIM     1024
#define NSTATES  20

#define KSPLIT   16
#define TKB      (KDIM / KSPLIT)   // 64 k-rows per block
#define TNB      256               // 256 cols per block (128 threads x 2 cols)
#define NTHREADS 128
#define NTILES   (NDIM / TNB)      // 4
#define RCHUNKS  2                 // row-chunk blocks per (ntile,state,kz)
#define ARRIVALS (KSPLIT * RCHUNKS)
#define RGP      20                // xs row stride in floats (80B, 16B-aligned)
#define RMAX     16

// cp.async pipeline
#define SKK      8                  // kk per stage
#define NSTG     3                  // stage buffers
#define NKST     (TKB / SKK)        // 8 stages per tile
#define STG_F    (SKK * TNB)        // floats per stage per tensor (2048)

#define KS_FLOATS (NSTG * STG_F)    // 6144
#define XS_FLOATS (TKB * RGP)       // 1280
#define SMEM_FLOATS (2 * KS_FLOATS + XS_FLOATS)
#define SMEM_BYTES  (SMEM_FLOATS * 4)   // 54,272 B

// Static scratch (allocation-free rules)
__device__ float    g_partial[(size_t)KSPLIT * BSZ * NDIM];    // 16 MB
__device__ unsigned g_arrive[NTILES * NSTATES];                // zero-init, self-resetting

// ---------------------------------------------------------------------------
// Packed f32x2 helpers (Blackwell FFMA2 — PTX-only path)
// ---------------------------------------------------------------------------
__device__ __forceinline__ unsigned long long u64_pack(unsigned a, unsigned b) {
    unsigned long long r;
    asm("mov.b64 %0, {%1,%2};" : "=l"(r) : "r"(a), "r"(b));
    return r;
}
__device__ __forceinline__ void u64_unpack(unsigned long long v, unsigned& a, unsigned& b) {
    asm("mov.b64 {%0,%1}, %2;" : "=r"(a), "=r"(b) : "l"(v));
}
__device__ __forceinline__ unsigned long long mul_f32x2(unsigned long long a, unsigned long long b) {
    unsigned long long r;
    asm("mul.rn.f32x2 %0, %1, %2;" : "=l"(r) : "l"(a), "l"(b));
    return r;
}
__device__ __forceinline__ unsigned long long fma_f32x2(unsigned long long a, unsigned long long b,
                                                        unsigned long long c) {
    unsigned long long r;
    asm("fma.rn.f32x2 %0, %1, %2, %3;" : "=l"(r) : "l"(a), "l"(b), "l"(c));
    return r;
}

// ---------------------------------------------------------------------------
// cp.async helpers
// ---------------------------------------------------------------------------
__device__ __forceinline__ void cp_async16(unsigned saddr, const void* gaddr) {
    asm volatile("cp.async.cg.shared.global [%0], [%1], 16;" :: "r"(saddr), "l"(gaddr));
}
__device__ __forceinline__ void cp_commit() {
    asm volatile("cp.async.commit_group;");
}
template<int N>
__device__ __forceinline__ void cp_wait() {
    asm volatile("cp.async.wait_group %0;" :: "n"(N));
}

// Issue one stage (8 kk x 256 cols, k + m tensors). 128 threads: half=tid/64
// covers alternating rows, each thread one 16B chunk per row, 4 passes.
__device__ __forceinline__ void issue_stage(
    unsigned ks_s, unsigned ms_s,
    const float* __restrict__ kg, const float* __restrict__ mg,
    int tid)
{
    const int half   = tid >> 6;          // 0/1
    const int coff   = (tid & 63) * 4;    // float col offset (16B granule)
    #pragma unroll
    for (int p = 0; p < 4; ++p) {
        const int row = p * 2 + half;
        const unsigned soff = (unsigned)(row * TNB + coff) * 4u;
        cp_async16(ks_s + soff, kg + (size_t)row * NDIM + coff);
        cp_async16(ms_s + soff, mg + (size_t)row * NDIM + coff);
    }
}

// ---------------------------------------------------------------------------
// One row-group of <=R rows [rg, rend): stage x transposed, then a 3-stage
// cp.async pipeline over the 64-k x 256-n tile; scatter split-K partials.
// ---------------------------------------------------------------------------
template<int R>
__device__ __forceinline__ void group_body(
    int rg, int rend, int tid, int kb,
    const float* __restrict__ x,
    const float* __restrict__ kbase,   // kern  + kb*NDIM + ntile*TNB
    const float* __restrict__ mbase,   // masks + (s*KDIM+kb)*NDIM + ntile*TNB
    const int*   srows,
    float* __restrict__ ks_buf,        // [NSTG][SKK][TNB]
    float* __restrict__ ms_buf,
    float* __restrict__ xs,            // [TKB][RGP]
    unsigned ks_u32, unsigned ms_u32,  // smem u32 addresses of the buffers
    float* __restrict__ pbase)
{
    // ---- stage x rows (transposed), zero-pad to R ----
    #pragma unroll 1
    for (int idx = tid; idx < TKB * R; idx += NTHREADS) {
        int r  = idx / TKB;
        int kk = idx % TKB;
        float v = 0.f;
        if (rg + r < rend) v = x[(size_t)srows[rg + r] * KDIM + kb + kk];
        xs[kk * RGP + r] = v;
    }
    __syncthreads();   // xs ready

    // ---- pipeline prologue: stages 0 and 1 in flight ----
    issue_stage(ks_u32, ms_u32, kbase, mbase, tid);
    cp_commit();
    issue_stage(ks_u32 + STG_F * 4, ms_u32 + STG_F * 4,
                kbase + (size_t)SKK * NDIM, mbase + (size_t)SKK * NDIM, tid);
    cp_commit();

    unsigned long long accA[R / 2];   // col n0,   row pairs packed
    unsigned long long accB[R / 2];   // col n0+1
    #pragma unroll
    for (int j = 0; j < R / 2; ++j) { accA[j] = 0ULL; accB[j] = 0ULL; }

    const int c2 = 2 * tid;           // this thread's col pair within tile

    #pragma unroll 1
    for (int st = 0; st < NKST; ++st) {
        cp_wait<1>();          // oldest pending (stage st) complete
        __syncthreads();       // its smem writes visible to all

        const int buf = st % NSTG;
        const float* ksp = ks_buf + buf * STG_F;
        const float* msp = ms_buf + buf * STG_F;
        const int kk0 = st * SKK;

        #pragma unroll
        for (int j = 0; j < SKK; ++j) {
            // k/m arrive pre-packed as f32x2 (8B-aligned LDS.64)
            const unsigned long long kraw =
                *reinterpret_cast<const unsigned long long*>(ksp + j * TNB + c2);
            const unsigned long long mraw =
                *reinterpret_cast<const unsigned long long*>(msp + j * TNB + c2);
            const unsigned long long wm = mul_f32x2(kraw, mraw);
            unsigned lo, hi;
            u64_unpack(wm, lo, hi);
            const unsigned long long wA = u64_pack(lo, lo);
            const unsigned long long wB = u64_pack(hi, hi);

            const ulonglong2* xp =
                reinterpret_cast<const ulonglong2*>(xs + (kk0 + j) * RGP);
            #pragma unroll
            for (int j4 = 0; j4 < R / 4; ++j4) {
                ulonglong2 xv = xp[j4];             // LDS.128 broadcast
                accA[2 * j4]     = fma_f32x2(xv.x, wA, accA[2 * j4]);
                accB[2 * j4]     = fma_f32x2(xv.x, wB, accB[2 * j4]);
                accA[2 * j4 + 1] = fma_f32x2(xv.y, wA, accA[2 * j4 + 1]);
                accB[2 * j4 + 1] = fma_f32x2(xv.y, wB, accB[2 * j4 + 1]);
            }
        }

        // refill the buffer we will need at st+2 (its old contents were
        // consumed before the barrier above), or commit an empty group to
        // keep the wait_group accounting advancing.
        const int nst = st + 2;
        if (nst < NKST) {
            const int nbuf = nst % NSTG;
            issue_stage(ks_u32 + nbuf * STG_F * 4, ms_u32 + nbuf * STG_F * 4,
                        kbase + (size_t)nst * SKK * NDIM,
                        mbase + (size_t)nst * SKK * NDIM, tid);
        }
        cp_commit();
    }

    // ---- scatter partials: g_partial[kz][row][n0..n0+1] ----
    #pragma unroll
    for (int j = 0; j < R / 2; ++j) {
        unsigned a0, a1, b0, b1;
        u64_unpack(accA[j], a0, a1);
        u64_unpack(accB[j], b0, b1);
        int r0 = rg + 2 * j, r1 = r0 + 1;
        if (r0 < rend) {
            float2 v = make_float2(__uint_as_float(a0), __uint_as_float(b0));
            *reinterpret_cast<float2*>(pbase + (size_t)srows[r0] * NDIM) = v;
        }
        if (r1 < rend) {
            float2 v = make_float2(__uint_as_float(a1), __uint_as_float(b1));
            *reinterpret_cast<float2*>(pbase + (size_t)srows[r1] * NDIM) = v;
        }
    }
    __syncthreads();   // xs/stage reuse safety across groups (ms>32 per chunk)
}

// ---------------------------------------------------------------------------
// Fused kernel. grid = (NTILES, NSTATES, KSPLIT*RCHUNKS), 128 threads.
// ---------------------------------------------------------------------------
__global__ void __launch_bounds__(NTHREADS, 4) mdl_fused(
    const float* __restrict__ x,
    const int*   __restrict__ state,
    const float* __restrict__ kern,
    const float* __restrict__ masks,
    float*       __restrict__ out)
{
    const int s     = blockIdx.y;
    const int ntile = blockIdx.x;
    const int kz    = blockIdx.z / RCHUNKS;
    const int rc    = blockIdx.z % RCHUNKS;
    const int tid   = threadIdx.x;

    extern __shared__ __align__(16) float dsm[];
    float* ks_buf = dsm;                        // [NSTG][SKK][TNB]
    float* ms_buf = dsm + KS_FLOATS;
    float* xs     = dsm + 2 * KS_FLOATS;        // [TKB][RGP]
    const unsigned ks_u32 = (unsigned)__cvta_generic_to_shared(ks_buf);
    const unsigned ms_u32 = (unsigned)__cvta_generic_to_shared(ms_buf);

    __shared__ int srows[BSZ];
    __shared__ int warp_cnt[8];
    __shared__ int s_ms;
    __shared__ int s_last;

    // ---- deterministic (ascending) row list via warp ballots ----
    {
        const int lane = tid & 31;
        const int w    = tid >> 5;                  // 4 warps
        const int r0   = w * 32 + lane;             // rows 0..127
        const int r1   = 128 + w * 32 + lane;       // rows 128..255
        const bool m0 = (state[r0] == s);
        const bool m1 = (state[r1] == s);
        const unsigned b0 = __ballot_sync(0xffffffffu, m0);
        const unsigned b1 = __ballot_sync(0xffffffffu, m1);
        if (lane == 0) { warp_cnt[w] = __popc(b0); warp_cnt[4 + w] = __popc(b1); }
        __syncthreads();
        int preA = 0, preB = 0, tot = 0;
        #pragma unroll
        for (int i = 0; i < 8; ++i) {
            int c = warp_cnt[i];
            if (i < w)              preA += c;
            if (i < 4 || i < 4 + w) preB += c;
            tot += c;
        }
        const unsigned ltmask = (1u << lane) - 1u;
        if (m0) srows[preA + __popc(b0 & ltmask)] = r0;
        if (m1) srows[preB + __popc(b1 & ltmask)] = r1;
        if (tid == 0) s_ms = tot;
        __syncthreads();
    }
    const int ms = s_ms;
    if (ms == 0) return;   // state absent -> no outputs, no arrivals needed

    // ---- this block's row chunk (deterministic, even split) ----
    int cs, ce;
    if (ms <= RMAX) { cs = (rc == 0) ? 0 : ms; ce = ms; }       // chunk1 empty
    else {
        int csz = (ms + RCHUNKS - 1) / RCHUNKS;
        cs = rc * csz; if (cs > ms) cs = ms;
        ce = cs + csz; if (ce > ms) ce = ms;
    }

    const int kb = kz * TKB;
    const int n0 = ntile * TNB + 2 * tid;
    const float* kbase = kern  + (size_t)kb * NDIM + ntile * TNB;
    const float* mbase = masks + ((size_t)s * KDIM + kb) * NDIM + ntile * TNB;
    float*       pbase = g_partial + (size_t)kz * BSZ * NDIM + n0;

    // ---- single padded pass (loop only if chunk > 16, i.e. ms > 32) ----
    while (cs < ce) {
        int left = ce - cs;
        if      (left <= 4)  { group_body<4 >(cs, ce, tid, kb, x, kbase, mbase, srows, ks_buf, ms_buf, xs, ks_u32, ms_u32, pbase); cs += 4;  }
        else if (left <= 8)  { group_body<8 >(cs, ce, tid, kb, x, kbase, mbase, srows, ks_buf, ms_buf, xs, ks_u32, ms_u32, pbase); cs += 8;  }
        else if (left <= 12) { group_body<12>(cs, ce, tid, kb, x, kbase, mbase, srows, ks_buf, ms_buf, xs, ks_u32, ms_u32, pbase); cs += 12; }
        else                 { group_body<16>(cs, ce, tid, kb, x, kbase, mbase, srows, ks_buf, ms_buf, xs, ks_u32, ms_u32, pbase); cs += 16; }
    }
    cp_wait<0>();   // drain trailing (possibly empty) groups before exit path

    // ---- split-K completion handshake (threadFenceReduction pattern) ----
    __threadfence();
    __syncthreads();
    const int region = ntile * NSTATES + s;
    if (tid == 0) {
        unsigned old = atomicAdd(&g_arrive[region], 1u);
        s_last = (old == ARRIVALS - 1);
        if (s_last) g_arrive[region] = 0;   // reset for next graph replay
    }
    __syncthreads();
    if (!s_last) return;
    __threadfence();   // acquire side

    // ---- last block per region: reduce KSPLIT partials + ReLU ----
    for (int r = 0; r < ms; ++r) {
        const int row = srows[r];
        const float* pr = g_partial + (size_t)row * NDIM + n0;
        float2 acc = *reinterpret_cast<const float2*>(pr);
        #pragma unroll
        for (int z = 1; z < KSPLIT; ++z) {
            float2 b = *reinterpret_cast<const float2*>(pr + (size_t)z * BSZ * NDIM);
            acc.x += b.x; acc.y += b.y;
        }
        acc.x = fmaxf(acc.x, 0.f);
        acc.y = fmaxf(acc.y, 0.f);
        *reinterpret_cast<float2*>(out + (size_t)row * NDIM + n0) = acc;
    }
}

// ---------------------------------------------------------------------------
extern "C" void kernel_launch(void* const* d_in, const int* in_sizes, int n_in,
                              void* d_out, int out_size)
{
    const float* x     = nullptr;
    const int*   state = nullptr;
    const float* kern  = nullptr;
    const float* masks = nullptr;
    for (int i = 0; i < n_in; ++i) {
        switch (in_sizes[i]) {
            case BSZ * KDIM:            x     = (const float*)d_in[i]; break;
            case BSZ:                   state = (const int*)  d_in[i]; break;
            case KDIM * NDIM:           kern  = (const float*)d_in[i]; break;
            case NSTATES * KDIM * NDIM: masks = (const float*)d_in[i]; break;
            default: break;
        }
    }
    float* out = (float*)d_out;

    // >48KB dynamic smem opt-in (host-side attribute set; not an allocation)
    cudaFuncSetAttribute(mdl_fused, cudaFuncAttributeMaxDynamicSharedMemorySize,
                         SMEM_BYTES);

    dim3 grid(NTILES, NSTATES, KSPLIT * RCHUNKS);
    mdl_fused<<<grid, NTHREADS, SMEM_BYTES>>>(x, state, kern, masks, out);
}

// round 15
// speedup vs baseline: 1.3677x; 1.0780x over previous
#include <cuda_runtime.h>
#include <cstdint>

// MaskedDenseLayer: BS=256, K=1024, N=1024, NUM_STATES=20
#define BSZ      256
#define KDIM     1024
#define NDIM     1024
#define NSTATES  20

#define KSPLIT   16
#define TKB      (KDIM / KSPLIT)   // 64 k-rows per block
#define TNB      256               // 256 cols per block (128 threads x 2 cols)
#define NTHREADS 128
#define NTILES   (NDIM / TNB)      // 4
#define ARRIVALS KSPLIT
#define RGP      20                // xs row stride in floats (80B, 16B-aligned)

// cp.async pipeline
#define SKK      8                  // kk per stage
#define NSTG     3                  // stage buffers
#define NKST     (TKB / SKK)        // 8 stages per tile
#define STG_F    (SKK * TNB)        // floats per stage per tensor (2048)

#define KS_FLOATS (NSTG * STG_F)    // 6144
#define XS_FLOATS (TKB * RGP)       // 1280
#define SMEM_FLOATS (2 * KS_FLOATS + XS_FLOATS)
#define SMEM_BYTES  (SMEM_FLOATS * 4)   // 54,272 B

// Static scratch (allocation-free rules)
__device__ float    g_partial[(size_t)KSPLIT * BSZ * NDIM];    // 16 MB
__device__ unsigned g_arrive[NTILES * NSTATES];                // zero-init, self-resetting

// ---------------------------------------------------------------------------
// Packed f32x2 helpers (Blackwell FFMA2 — PTX-only path)
// ---------------------------------------------------------------------------
__device__ __forceinline__ unsigned long long u64_pack(unsigned a, unsigned b) {
    unsigned long long r;
    asm("mov.b64 %0, {%1,%2};" : "=l"(r) : "r"(a), "r"(b));
    return r;
}
__device__ __forceinline__ void u64_unpack(unsigned long long v, unsigned& a, unsigned& b) {
    asm("mov.b64 {%0,%1}, %2;" : "=r"(a), "=r"(b) : "l"(v));
}
__device__ __forceinline__ unsigned long long mul_f32x2(unsigned long long a, unsigned long long b) {
    unsigned long long r;
    asm("mul.rn.f32x2 %0, %1, %2;" : "=l"(r) : "l"(a), "l"(b));
    return r;
}
__device__ __forceinline__ unsigned long long fma_f32x2(unsigned long long a, unsigned long long b,
                                                        unsigned long long c) {
    unsigned long long r;
    asm("fma.rn.f32x2 %0, %1, %2, %3;" : "=l"(r) : "l"(a), "l"(b), "l"(c));
    return r;
}

// ---------------------------------------------------------------------------
// cp.async helpers
// ---------------------------------------------------------------------------
__device__ __forceinline__ void cp_async16(unsigned saddr, const void* gaddr) {
    asm volatile("cp.async.cg.shared.global [%0], [%1], 16;" :: "r"(saddr), "l"(gaddr));
}
__device__ __forceinline__ void cp_commit() {
    asm volatile("cp.async.commit_group;");
}
template<int N>
__device__ __forceinline__ void cp_wait() {
    asm volatile("cp.async.wait_group %0;" :: "n"(N));
}

// WARP-LOCAL stage issue: warp w copies ONLY its own 64-col slice of the
// 8-row k and m stage tiles. Per lane: 4 passes x (1 k + 1 m) 16B cp.async.
// Lane l, pass p -> row = 2p + l/16, 16B-chunk = l%16 within the 64-col slice.
// The warp later consumes exactly this slice (cols 64w + [0,64)), so the
// visibility handshake is wait_group + __syncwarp — no block barrier.
__device__ __forceinline__ void issue_warp_stage(
    unsigned ks_s, unsigned ms_s,
    const float* __restrict__ kg, const float* __restrict__ mg,
    int wid, int lane)
{
    const int wcb  = wid * 64;             // warp col base (floats)
    const int cch  = (lane & 15) * 4;      // chunk col offset (floats)
    const int rhalf = lane >> 4;           // 0/1
    #pragma unroll
    for (int p = 0; p < 4; ++p) {
        const int row = p * 2 + rhalf;
        const unsigned soff = (unsigned)(row * TNB + wcb + cch) * 4u;
        const size_t   goff = (size_t)row * NDIM + wcb + cch;
        cp_async16(ks_s + soff, kg + goff);
        cp_async16(ms_s + soff, mg + goff);
    }
}

// ---------------------------------------------------------------------------
// One row-group of <=R rows [rg, rend): stage x transposed (block-wide), then
// a per-warp 3-stage cp.async pipeline over the 64-k x 256-n tile (warps run
// decoupled: only __syncwarp in the mainloop); scatter split-K partials.
// ---------------------------------------------------------------------------
template<int R>
__device__ __forceinline__ void group_body(
    int rg, int rend, int tid, int kb,
    const float* __restrict__ x,
    const float* __restrict__ kbase,   // kern  + kb*NDIM + ntile*TNB
    const float* __restrict__ mbase,   // masks + (s*KDIM+kb)*NDIM + ntile*TNB
    const int*   srows,
    float* __restrict__ xs,            // [TKB][RGP]
    unsigned ks_u32, unsigned ms_u32,  // smem u32 addresses of stage buffers
    float* __restrict__ pbase)
{
    const int wid  = tid >> 5;
    const int lane = tid & 31;

    // ---- stage x rows (transposed), zero-pad to R (block-wide) ----
    __syncthreads();   // prior group's xs readers done
    #pragma unroll 1
    for (int idx = tid; idx < TKB * R; idx += NTHREADS) {
        int r  = idx / TKB;
        int kk = idx % TKB;
        float v = 0.f;
        if (rg + r < rend) v = x[(size_t)srows[rg + r] * KDIM + kb + kk];
        xs[kk * RGP + r] = v;
    }
    __syncthreads();   // xs ready for all warps

    // ---- per-warp pipeline prologue: stages 0,1 in flight ----
    issue_warp_stage(ks_u32, ms_u32, kbase, mbase, wid, lane);
    cp_commit();
    issue_warp_stage(ks_u32 + STG_F * 4, ms_u32 + STG_F * 4,
                     kbase + (size_t)SKK * NDIM, mbase + (size_t)SKK * NDIM,
                     wid, lane);
    cp_commit();

    unsigned long long accA[R / 2];   // col n0,   row pairs packed
    unsigned long long accB[R / 2];   // col n0+1
    #pragma unroll
    for (int j = 0; j < R / 2; ++j) { accA[j] = 0ULL; accB[j] = 0ULL; }

    const int c2 = 2 * tid;           // this thread's col pair (inside its warp's slice)

    #pragma unroll 1
    for (int st = 0; st < NKST; ++st) {
        cp_wait<1>();          // own stage-st copies complete
        __syncwarp();          // whole warp's slice copies complete & visible

        const unsigned bofs = (unsigned)((st % NSTG) * STG_F) * 4u;
        const int kk0 = st * SKK;

        #pragma unroll
        for (int j = 0; j < SKK; ++j) {
            unsigned long long kraw, mraw;
            const unsigned a = (unsigned)((j * TNB + c2) * 4);
            asm volatile("ld.shared.b64 %0, [%1];" : "=l"(kraw) : "r"(ks_u32 + bofs + a));
            asm volatile("ld.shared.b64 %0, [%1];" : "=l"(mraw) : "r"(ms_u32 + bofs + a));
            const unsigned long long wm = mul_f32x2(kraw, mraw);
            unsigned lo, hi;
            u64_unpack(wm, lo, hi);
            const unsigned long long wA = u64_pack(lo, lo);
            const unsigned long long wB = u64_pack(hi, hi);

            const ulonglong2* xp =
                reinterpret_cast<const ulonglong2*>(xs + (kk0 + j) * RGP);
            #pragma unroll
            for (int j4 = 0; j4 < R / 4; ++j4) {
                ulonglong2 xv = xp[j4];             // LDS.128 broadcast
                accA[2 * j4]     = fma_f32x2(xv.x, wA, accA[2 * j4]);
                accB[2 * j4]     = fma_f32x2(xv.x, wB, accB[2 * j4]);
                accA[2 * j4 + 1] = fma_f32x2(xv.y, wA, accA[2 * j4 + 1]);
                accB[2 * j4 + 1] = fma_f32x2(xv.y, wB, accB[2 * j4 + 1]);
            }
        }

        // refill buffer needed at st+2 (this warp consumed its old contents
        // at st-1, program order), or commit empty to advance accounting.
        const int nst = st + 2;
        if (nst < NKST) {
            const unsigned nofs = (unsigned)((nst % NSTG) * STG_F) * 4u;
            issue_warp_stage(ks_u32 + nofs, ms_u32 + nofs,
                             kbase + (size_t)nst * SKK * NDIM,
                             mbase + (size_t)nst * SKK * NDIM, wid, lane);
        }
        cp_commit();
    }

    // ---- scatter partials: g_partial[kz][row][n0..n0+1] ----
    #pragma unroll
    for (int j = 0; j < R / 2; ++j) {
        unsigned a0, a1, b0, b1;
        u64_unpack(accA[j], a0, a1);
        u64_unpack(accB[j], b0, b1);
        int r0 = rg + 2 * j, r1 = r0 + 1;
        if (r0 < rend) {
            float2 v = make_float2(__uint_as_float(a0), __uint_as_float(b0));
            *reinterpret_cast<float2*>(pbase + (size_t)srows[r0] * NDIM) = v;
        }
        if (r1 < rend) {
            float2 v = make_float2(__uint_as_float(a1), __uint_as_float(b1));
            *reinterpret_cast<float2*>(pbase + (size_t)srows[r1] * NDIM) = v;
        }
    }
}

// ---------------------------------------------------------------------------
// Fused kernel. grid = (NTILES, NSTATES, KSPLIT), 128 threads.
// One block per (ntile, state, kz) handles ALL rows of its state.
// ---------------------------------------------------------------------------
__global__ void __launch_bounds__(NTHREADS, 4) mdl_fused(
    const float* __restrict__ x,
    const int*   __restrict__ state,
    const float* __restrict__ kern,
    const float* __restrict__ masks,
    float*       __restrict__ out)
{
    const int s     = blockIdx.y;
    const int ntile = blockIdx.x;
    const int kz    = blockIdx.z;
    const int tid   = threadIdx.x;

    extern __shared__ __align__(16) float dsm[];
    float* ks_buf = dsm;                        // [NSTG][SKK][TNB]
    float* ms_buf = dsm + KS_FLOATS;
    float* xs     = dsm + 2 * KS_FLOATS;        // [TKB][RGP]
    const unsigned ks_u32 = (unsigned)__cvta_generic_to_shared(ks_buf);
    const unsigned ms_u32 = (unsigned)__cvta_generic_to_shared(ms_buf);

    __shared__ int srows[BSZ];
    __shared__ int warp_cnt[8];
    __shared__ int s_ms;
    __shared__ int s_last;

    // ---- deterministic (ascending) row list via warp ballots ----
    {
        const int lane = tid & 31;
        const int w    = tid >> 5;                  // 4 warps
        const int r0   = w * 32 + lane;             // rows 0..127
        const int r1   = 128 + w * 32 + lane;       // rows 128..255
        const bool m0 = (state[r0] == s);
        const bool m1 = (state[r1] == s);
        const unsigned b0 = __ballot_sync(0xffffffffu, m0);
        const unsigned b1 = __ballot_sync(0xffffffffu, m1);
        if (lane == 0) { warp_cnt[w] = __popc(b0); warp_cnt[4 + w] = __popc(b1); }
        __syncthreads();
        int preA = 0, preB = 0, tot = 0;
        #pragma unroll
        for (int i = 0; i < 8; ++i) {
            int c = warp_cnt[i];
            if (i < w)              preA += c;
            if (i < 4 || i < 4 + w) preB += c;
            tot += c;
        }
        const unsigned ltmask = (1u << lane) - 1u;
        if (m0) srows[preA + __popc(b0 & ltmask)] = r0;
        if (m1) srows[preB + __popc(b1 & ltmask)] = r1;
        if (tid == 0) s_ms = tot;
        __syncthreads();
    }
    const int ms = s_ms;
    if (ms == 0) return;   // state absent -> no outputs, no arrivals needed

    const int kb = kz * TKB;
    const int n0 = ntile * TNB + 2 * tid;
    const float* kbase = kern  + (size_t)kb * NDIM + ntile * TNB;
    const float* mbase = masks + ((size_t)s * KDIM + kb) * NDIM + ntile * TNB;
    float*       pbase = g_partial + (size_t)kz * BSZ * NDIM + n0;

    // ---- all rows of this state, groups of <=16 (single group if ms<=16) ----
    int cs = 0;
    while (cs < ms) {
        int left = ms - cs;
        if (left <= 8) { group_body<8 >(cs, ms, tid, kb, x, kbase, mbase, srows, xs, ks_u32, ms_u32, pbase); cs += 8;  }
        else           { group_body<16>(cs, ms, tid, kb, x, kbase, mbase, srows, xs, ks_u32, ms_u32, pbase); cs += 16; }
    }
    cp_wait<0>();   // drain trailing (possibly empty) groups before exit path

    // ---- split-K completion handshake (threadFenceReduction pattern) ----
    __threadfence();
    __syncthreads();
    const int region = ntile * NSTATES + s;
    if (tid == 0) {
        unsigned old = atomicAdd(&g_arrive[region], 1u);
        s_last = (old == ARRIVALS - 1);
        if (s_last) g_arrive[region] = 0;   // reset for next graph replay
    }
    __syncthreads();
    if (!s_last) return;
    __threadfence();   // acquire side

    // ---- last block per region: reduce KSPLIT partials + ReLU ----
    for (int r = 0; r < ms; ++r) {
        const int row = srows[r];
        const float* pr = g_partial + (size_t)row * NDIM + n0;
        float2 acc = *reinterpret_cast<const float2*>(pr);
        #pragma unroll
        for (int z = 1; z < KSPLIT; ++z) {
            float2 b = *reinterpret_cast<const float2*>(pr + (size_t)z * BSZ * NDIM);
            acc.x += b.x; acc.y += b.y;
        }
        acc.x = fmaxf(acc.x, 0.f);
        acc.y = fmaxf(acc.y, 0.f);
        *reinterpret_cast<float2*>(out + (size_t)row * NDIM + n0) = acc;
    }
}

// ---------------------------------------------------------------------------
extern "C" void kernel_launch(void* const* d_in, const int* in_sizes, int n_in,
                              void* d_out, int out_size)
{
    const float* x     = nullptr;
    const int*   state = nullptr;
    const float* kern  = nullptr;
    const float* masks = nullptr;
    for (int i = 0; i < n_in; ++i) {
        switch (in_sizes[i]) {
            case BSZ * KDIM:            x     = (const float*)d_in[i]; break;
            case BSZ:                   state = (const int*)  d_in[i]; break;
            case KDIM * NDIM:           kern  = (const float*)d_in[i]; break;
            case NSTATES * KDIM * NDIM: masks = (const float*)d_in[i]; break;
            default: break;
        }
    }
    float* out = (float*)d_out;

    // >48KB dynamic smem opt-in (host-side attribute set; not an allocation)
    cudaFuncSetAttribute(mdl_fused, cudaFuncAttributeMaxDynamicSharedMemorySize,
                         SMEM_BYTES);

    dim3 grid(NTILES, NSTATES, KSPLIT);
    mdl_fused<<<grid, NTHREADS, SMEM_BYTES>>>(x, state, kern, masks, out);
}

// round 16
// speedup vs baseline: 1.4544x; 1.0634x over previous
#include <cuda_runtime.h>
#include <cstdint>

// MaskedDenseLayer: BS=256, K=1024, N=1024, NUM_STATES=20
#define BSZ      256
#define KDIM     1024
#define NDIM     1024
#define NSTATES  20

#define KSPLIT   16
#define TKB      (KDIM / KSPLIT)   // 64 k-rows per block
#define TNB      256               // 256 cols per block (128 threads x 2 cols)
#define NTHREADS 128
#define NTILES   (NDIM / TNB)      // 4
#define ARRIVALS KSPLIT
#define RGP      20                // xs row stride in floats (80B, 16B-aligned)

// cp.async pipeline (warp-private double buffer)
#define SKK      8                  // kk per stage
#define NSTG     2                  // stage buffers (double-buffer; warp-private)
#define NKST     (TKB / SKK)        // 8 stages per tile
#define STG_F    (SKK * TNB)        // floats per stage per tensor (2048)

#define KS_FLOATS (NSTG * STG_F)    // 4096
#define XS_FLOATS (TKB * RGP)       // 1280
#define SMEM_FLOATS (2 * KS_FLOATS + XS_FLOATS)
#define SMEM_BYTES  (SMEM_FLOATS * 4)   // 37,888 B

// Static scratch (allocation-free rules)
__device__ float    g_partial[(size_t)KSPLIT * BSZ * NDIM];    // 16 MB
__device__ unsigned g_arrive[NTILES * NSTATES];                // zero-init, self-resetting

// ---------------------------------------------------------------------------
// Packed f32x2 helpers (Blackwell FFMA2 — PTX-only path)
// ---------------------------------------------------------------------------
__device__ __forceinline__ unsigned long long u64_pack(unsigned a, unsigned b) {
    unsigned long long r;
    asm("mov.b64 %0, {%1,%2};" : "=l"(r) : "r"(a), "r"(b));
    return r;
}
__device__ __forceinline__ void u64_unpack(unsigned long long v, unsigned& a, unsigned& b) {
    asm("mov.b64 {%0,%1}, %2;" : "=r"(a), "=r"(b) : "l"(v));
}
__device__ __forceinline__ unsigned long long mul_f32x2(unsigned long long a, unsigned long long b) {
    unsigned long long r;
    asm("mul.rn.f32x2 %0, %1, %2;" : "=l"(r) : "l"(a), "l"(b));
    return r;
}
__device__ __forceinline__ unsigned long long fma_f32x2(unsigned long long a, unsigned long long b,
                                                        unsigned long long c) {
    unsigned long long r;
    asm("fma.rn.f32x2 %0, %1, %2, %3;" : "=l"(r) : "l"(a), "l"(b), "l"(c));
    return r;
}

// ---------------------------------------------------------------------------
// cp.async helpers
// ---------------------------------------------------------------------------
__device__ __forceinline__ void cp_async16(unsigned saddr, const void* gaddr) {
    asm volatile("cp.async.cg.shared.global [%0], [%1], 16;" :: "r"(saddr), "l"(gaddr));
}
__device__ __forceinline__ void cp_commit() {
    asm volatile("cp.async.commit_group;");
}
template<int N>
__device__ __forceinline__ void cp_wait() {
    asm volatile("cp.async.wait_group %0;" :: "n"(N));
}

// WARP-LOCAL stage issue: warp w copies ONLY its own 64-col slice of the
// 8-row k and m stage tiles. Per lane: 4 passes x (1 k + 1 m) 16B cp.async.
// The warp later consumes exactly this slice, so the visibility handshake is
// wait_group + __syncwarp — no block barrier, and double-buffering is safe
// (refill follows this warp's own consumption in program order).
__device__ __forceinline__ void issue_warp_stage(
    unsigned ks_s, unsigned ms_s,
    const float* __restrict__ kg, const float* __restrict__ mg,
    int wid, int lane)
{
    const int wcb  = wid * 64;             // warp col base (floats)
    const int cch  = (lane & 15) * 4;      // chunk col offset (floats)
    const int rhalf = lane >> 4;           // 0/1
    #pragma unroll
    for (int p = 0; p < 4; ++p) {
        const int row = p * 2 + rhalf;
        const unsigned soff = (unsigned)(row * TNB + wcb + cch) * 4u;
        const size_t   goff = (size_t)row * NDIM + wcb + cch;
        cp_async16(ks_s + soff, kg + goff);
        cp_async16(ms_s + soff, mg + goff);
    }
}

// ---------------------------------------------------------------------------
// One row-group of <=R rows [rg, rend): stage x transposed (block-wide), then
// a per-warp double-buffered cp.async pipeline over the 64-k x 256-n tile
// (warps fully decoupled in the mainloop); scatter split-K partials.
// ---------------------------------------------------------------------------
template<int R>
__device__ __forceinline__ void group_body(
    int rg, int rend, int tid, int kb,
    const float* __restrict__ x,
    const float* __restrict__ kbase,   // kern  + kb*NDIM + ntile*TNB
    const float* __restrict__ mbase,   // masks + (s*KDIM+kb)*NDIM + ntile*TNB
    const int*   srows,
    float* __restrict__ xs,            // [TKB][RGP]
    unsigned ks_u32, unsigned ms_u32,  // smem u32 addresses of stage buffers
    float* __restrict__ pbase)
{
    const int wid  = tid >> 5;
    const int lane = tid & 31;

    // ---- stage x rows (transposed), zero-pad to R (block-wide) ----
    __syncthreads();   // prior group's xs readers done
    #pragma unroll 1
    for (int idx = tid; idx < TKB * R; idx += NTHREADS) {
        int r  = idx / TKB;
        int kk = idx % TKB;
        float v = 0.f;
        if (rg + r < rend) v = x[(size_t)srows[rg + r] * KDIM + kb + kk];
        xs[kk * RGP + r] = v;
    }
    __syncthreads();   // xs ready for all warps

    // ---- per-warp pipeline prologue: stages 0,1 in flight ----
    issue_warp_stage(ks_u32, ms_u32, kbase, mbase, wid, lane);
    cp_commit();
    issue_warp_stage(ks_u32 + STG_F * 4, ms_u32 + STG_F * 4,
                     kbase + (size_t)SKK * NDIM, mbase + (size_t)SKK * NDIM,
                     wid, lane);
    cp_commit();

    unsigned long long accA[R / 2];   // col n0,   row pairs packed
    unsigned long long accB[R / 2];   // col n0+1
    #pragma unroll
    for (int j = 0; j < R / 2; ++j) { accA[j] = 0ULL; accB[j] = 0ULL; }

    const int c2 = 2 * tid;           // this thread's col pair (inside its warp's slice)

    #pragma unroll 1
    for (int st = 0; st < NKST; ++st) {
        cp_wait<1>();          // own stage-st copies complete
        __syncwarp();          // whole warp's slice copies complete & visible

        const unsigned bofs = (unsigned)((st % NSTG) * STG_F) * 4u;
        const int kk0 = st * SKK;

        #pragma unroll
        for (int j = 0; j < SKK; ++j) {
            unsigned long long kraw, mraw;
            const unsigned a = (unsigned)((j * TNB + c2) * 4);
            asm volatile("ld.shared.b64 %0, [%1];" : "=l"(kraw) : "r"(ks_u32 + bofs + a));
            asm volatile("ld.shared.b64 %0, [%1];" : "=l"(mraw) : "r"(ms_u32 + bofs + a));
            const unsigned long long wm = mul_f32x2(kraw, mraw);
            unsigned lo, hi;
            u64_unpack(wm, lo, hi);
            const unsigned long long wA = u64_pack(lo, lo);
            const unsigned long long wB = u64_pack(hi, hi);

            const ulonglong2* xp =
                reinterpret_cast<const ulonglong2*>(xs + (kk0 + j) * RGP);
            #pragma unroll
            for (int j4 = 0; j4 < R / 4; ++j4) {
                ulonglong2 xv = xp[j4];             // LDS.128 broadcast
                accA[2 * j4]     = fma_f32x2(xv.x, wA, accA[2 * j4]);
                accB[2 * j4]     = fma_f32x2(xv.x, wB, accB[2 * j4]);
                accA[2 * j4 + 1] = fma_f32x2(xv.y, wA, accA[2 * j4 + 1]);
                accB[2 * j4 + 1] = fma_f32x2(xv.y, wB, accB[2 * j4 + 1]);
            }
        }

        // refill the buffer just consumed (warp-private: safe by program
        // order), or commit an empty group to keep the accounting advancing.
        const int nst = st + 2;
        if (nst < NKST) {
            const unsigned nofs = (unsigned)((nst % NSTG) * STG_F) * 4u;
            issue_warp_stage(ks_u32 + nofs, ms_u32 + nofs,
                             kbase + (size_t)nst * SKK * NDIM,
                             mbase + (size_t)nst * SKK * NDIM, wid, lane);
        }
        cp_commit();
    }

    // ---- scatter partials: g_partial[kz][row][n0..n0+1] ----
    #pragma unroll
    for (int j = 0; j < R / 2; ++j) {
        unsigned a0, a1, b0, b1;
        u64_unpack(accA[j], a0, a1);
        u64_unpack(accB[j], b0, b1);
        int r0 = rg + 2 * j, r1 = r0 + 1;
        if (r0 < rend) {
            float2 v = make_float2(__uint_as_float(a0), __uint_as_float(b0));
            *reinterpret_cast<float2*>(pbase + (size_t)srows[r0] * NDIM) = v;
        }
        if (r1 < rend) {
            float2 v = make_float2(__uint_as_float(a1), __uint_as_float(b1));
            *reinterpret_cast<float2*>(pbase + (size_t)srows[r1] * NDIM) = v;
        }
    }
}

// ---------------------------------------------------------------------------
// Fused kernel. grid = (NTILES, NSTATES, KSPLIT), 128 threads.
// __launch_bounds__(128, 5): cap regs ~102 so 5 blocks/SM fit (smem 37.9KB).
// ---------------------------------------------------------------------------
__global__ void __launch_bounds__(NTHREADS, 5) mdl_fused(
    const float* __restrict__ x,
    const int*   __restrict__ state,
    const float* __restrict__ kern,
    const float* __restrict__ masks,
    float*       __restrict__ out)
{
    const int s     = blockIdx.y;
    const int ntile = blockIdx.x;
    const int kz    = blockIdx.z;
    const int tid   = threadIdx.x;

    extern __shared__ __align__(16) float dsm[];
    float* ks_buf = dsm;                        // [NSTG][SKK][TNB]
    float* ms_buf = dsm + KS_FLOATS;
    float* xs     = dsm + 2 * KS_FLOATS;        // [TKB][RGP]
    const unsigned ks_u32 = (unsigned)__cvta_generic_to_shared(ks_buf);
    const unsigned ms_u32 = (unsigned)__cvta_generic_to_shared(ms_buf);

    __shared__ int srows[BSZ];
    __shared__ int warp_cnt[8];
    __shared__ int s_ms;
    __shared__ int s_last;

    // ---- deterministic (ascending) row list via warp ballots ----
    {
        const int lane = tid & 31;
        const int w    = tid >> 5;                  // 4 warps
        const int r0   = w * 32 + lane;             // rows 0..127
        const int r1   = 128 + w * 32 + lane;       // rows 128..255
        const bool m0 = (state[r0] == s);
        const bool m1 = (state[r1] == s);
        const unsigned b0 = __ballot_sync(0xffffffffu, m0);
        const unsigned b1 = __ballot_sync(0xffffffffu, m1);
        if (lane == 0) { warp_cnt[w] = __popc(b0); warp_cnt[4 + w] = __popc(b1); }
        __syncthreads();
        int preA = 0, preB = 0, tot = 0;
        #pragma unroll
        for (int i = 0; i < 8; ++i) {
            int c = warp_cnt[i];
            if (i < w)              preA += c;
            if (i < 4 || i < 4 + w) preB += c;
            tot += c;
        }
        const unsigned ltmask = (1u << lane) - 1u;
        if (m0) srows[preA + __popc(b0 & ltmask)] = r0;
        if (m1) srows[preB + __popc(b1 & ltmask)] = r1;
        if (tid == 0) s_ms = tot;
        __syncthreads();
    }
    const int ms = s_ms;
    if (ms == 0) return;   // state absent -> no outputs, no arrivals needed

    const int kb = kz * TKB;
    const int n0 = ntile * TNB + 2 * tid;
    const float* kbase = kern  + (size_t)kb * NDIM + ntile * TNB;
    const float* mbase = masks + ((size_t)s * KDIM + kb) * NDIM + ntile * TNB;
    float*       pbase = g_partial + (size_t)kz * BSZ * NDIM + n0;

    // ---- all rows of this state, groups of <=16 (single group if ms<=16) ----
    int cs = 0;
    while (cs < ms) {
        int left = ms - cs;
        if (left <= 8) { group_body<8 >(cs, ms, tid, kb, x, kbase, mbase, srows, xs, ks_u32, ms_u32, pbase); cs += 8;  }
        else           { group_body<16>(cs, ms, tid, kb, x, kbase, mbase, srows, xs, ks_u32, ms_u32, pbase); cs += 16; }
    }
    cp_wait<0>();   // drain trailing (possibly empty) groups before exit path

    // ---- split-K completion handshake (threadFenceReduction pattern) ----
    __threadfence();
    __syncthreads();
    const int region = ntile * NSTATES + s;
    if (tid == 0) {
        unsigned old = atomicAdd(&g_arrive[region], 1u);
        s_last = (old == ARRIVALS - 1);
        if (s_last) g_arrive[region] = 0;   // reset for next graph replay
    }
    __syncthreads();
    if (!s_last) return;
    __threadfence();   // acquire side

    // ---- last block per region: reduce KSPLIT partials + ReLU ----
    for (int r = 0; r < ms; ++r) {
        const int row = srows[r];
        const float* pr = g_partial + (size_t)row * NDIM + n0;
        float2 acc = *reinterpret_cast<const float2*>(pr);
        #pragma unroll
        for (int z = 1; z < KSPLIT; ++z) {
            float2 b = *reinterpret_cast<const float2*>(pr + (size_t)z * BSZ * NDIM);
            acc.x += b.x; acc.y += b.y;
        }
        acc.x = fmaxf(acc.x, 0.f);
        acc.y = fmaxf(acc.y, 0.f);
        *reinterpret_cast<float2*>(out + (size_t)row * NDIM + n0) = acc;
    }
}

// ---------------------------------------------------------------------------
extern "C" void kernel_launch(void* const* d_in, const int* in_sizes, int n_in,
                              void* d_out, int out_size)
{
    const float* x     = nullptr;
    const int*   state = nullptr;
    const float* kern  = nullptr;
    const float* masks = nullptr;
    for (int i = 0; i < n_in; ++i) {
        switch (in_sizes[i]) {
            case BSZ * KDIM:            x     = (const float*)d_in[i]; break;
            case BSZ:                   state = (const int*)  d_in[i]; break;
            case KDIM * NDIM:           kern  = (const float*)d_in[i]; break;
            case NSTATES * KDIM * NDIM: masks = (const float*)d_in[i]; break;
            default: break;
        }
    }
    float* out = (float*)d_out;

    // >48KB not needed anymore (37.9KB), but harmless to allow
    cudaFuncSetAttribute(mdl_fused, cudaFuncAttributeMaxDynamicSharedMemorySize,
                         SMEM_BYTES);

    dim3 grid(NTILES, NSTATES, KSPLIT);
    mdl_fused<<<grid, NTHREADS, SMEM_BYTES>>>(x, state, kern, masks, out);
}

// round 17
// speedup vs baseline: 1.4613x; 1.0048x over previous
#include <cuda_runtime.h>
#include <cstdint>

// MaskedDenseLayer: BS=256, K=1024, N=1024, NUM_STATES=20
#define BSZ      256
#define KDIM     1024
#define NDIM     1024
#define NSTATES  20

#define KSPLIT   8
#define TKB      (KDIM / KSPLIT)   // 128 k-rows per block
#define TNB      256               // 256 cols per block (128 threads x 2 cols)
#define NTHREADS 128
#define NTILES   (NDIM / TNB)      // 4
#define ARRIVALS KSPLIT
#define RGP      20                // xs row stride in floats (80B, 16B-aligned)

// cp.async pipeline (warp-private double buffer)
#define SKK      8                  // kk per stage
#define NSTG     2                  // stage buffers (double-buffer; warp-private)
#define NKST     (TKB / SKK)        // 16 stages per tile
#define STG_F    (SKK * TNB)        // floats per stage per tensor (2048)

#define KS_FLOATS (NSTG * STG_F)    // 4096
#define XS_FLOATS (TKB * RGP)       // 2560
#define SMEM_FLOATS (2 * KS_FLOATS + XS_FLOATS)
#define SMEM_BYTES  (SMEM_FLOATS * 4)   // 43,008 B -> 5 blocks/SM (215KB/228KB)

// Static scratch (allocation-free rules)
__device__ float    g_partial[(size_t)KSPLIT * BSZ * NDIM];    // 8 MB
__device__ unsigned g_arrive[NTILES * NSTATES];                // zero-init, self-resetting

// ---------------------------------------------------------------------------
// Packed f32x2 helpers (Blackwell FFMA2 — PTX-only path)
// ---------------------------------------------------------------------------
__device__ __forceinline__ unsigned long long u64_pack(unsigned a, unsigned b) {
    unsigned long long r;
    asm("mov.b64 %0, {%1,%2};" : "=l"(r) : "r"(a), "r"(b));
    return r;
}
__device__ __forceinline__ void u64_unpack(unsigned long long v, unsigned& a, unsigned& b) {
    asm("mov.b64 {%0,%1}, %2;" : "=r"(a), "=r"(b) : "l"(v));
}
__device__ __forceinline__ unsigned long long mul_f32x2(unsigned long long a, unsigned long long b) {
    unsigned long long r;
    asm("mul.rn.f32x2 %0, %1, %2;" : "=l"(r) : "l"(a), "l"(b));
    return r;
}
__device__ __forceinline__ unsigned long long fma_f32x2(unsigned long long a, unsigned long long b,
                                                        unsigned long long c) {
    unsigned long long r;
    asm("fma.rn.f32x2 %0, %1, %2, %3;" : "=l"(r) : "l"(a), "l"(b), "l"(c));
    return r;
}

// ---------------------------------------------------------------------------
// cp.async helpers
// ---------------------------------------------------------------------------
__device__ __forceinline__ void cp_async16(unsigned saddr, const void* gaddr) {
    asm volatile("cp.async.cg.shared.global [%0], [%1], 16;" :: "r"(saddr), "l"(gaddr));
}
__device__ __forceinline__ void cp_commit() {
    asm volatile("cp.async.commit_group;");
}
template<int N>
__device__ __forceinline__ void cp_wait() {
    asm volatile("cp.async.wait_group %0;" :: "n"(N));
}

// WARP-LOCAL stage issue: warp w copies ONLY its own 64-col slice of the
// 8-row k and m stage tiles. Per lane: 4 passes x (1 k + 1 m) 16B cp.async.
// The warp later consumes exactly this slice, so the visibility handshake is
// wait_group + __syncwarp — no block barrier, and double-buffering is safe
// (refill follows this warp's own consumption in program order).
__device__ __forceinline__ void issue_warp_stage(
    unsigned ks_s, unsigned ms_s,
    const float* __restrict__ kg, const float* __restrict__ mg,
    int wid, int lane)
{
    const int wcb  = wid * 64;             // warp col base (floats)
    const int cch  = (lane & 15) * 4;      // chunk col offset (floats)
    const int rhalf = lane >> 4;           // 0/1
    #pragma unroll
    for (int p = 0; p < 4; ++p) {
        const int row = p * 2 + rhalf;
        const unsigned soff = (unsigned)(row * TNB + wcb + cch) * 4u;
        const size_t   goff = (size_t)row * NDIM + wcb + cch;
        cp_async16(ks_s + soff, kg + goff);
        cp_async16(ms_s + soff, mg + goff);
    }
}

// ---------------------------------------------------------------------------
// One row-group of <=R rows [rg, rend): stage x transposed (block-wide), then
// a per-warp double-buffered cp.async pipeline over the 128-k x 256-n tile
// (warps fully decoupled in the mainloop); scatter split-K partials.
// ---------------------------------------------------------------------------
template<int R>
__device__ __forceinline__ void group_body(
    int rg, int rend, int tid, int kb,
    const float* __restrict__ x,
    const float* __restrict__ kbase,   // kern  + kb*NDIM + ntile*TNB
    const float* __restrict__ mbase,   // masks + (s*KDIM+kb)*NDIM + ntile*TNB
    const int*   srows,
    float* __restrict__ xs,            // [TKB][RGP]
    unsigned ks_u32, unsigned ms_u32,  // smem u32 addresses of stage buffers
    float* __restrict__ pbase)
{
    const int wid  = tid >> 5;
    const int lane = tid & 31;

    // ---- stage x rows (transposed), zero-pad to R (block-wide) ----
    __syncthreads();   // prior group's xs readers done
    #pragma unroll 1
    for (int idx = tid; idx < TKB * R; idx += NTHREADS) {
        int r  = idx / TKB;
        int kk = idx % TKB;
        float v = 0.f;
        if (rg + r < rend) v = x[(size_t)srows[rg + r] * KDIM + kb + kk];
        xs[kk * RGP + r] = v;
    }
    __syncthreads();   // xs ready for all warps

    // ---- per-warp pipeline prologue: stages 0,1 in flight ----
    issue_warp_stage(ks_u32, ms_u32, kbase, mbase, wid, lane);
    cp_commit();
    issue_warp_stage(ks_u32 + STG_F * 4, ms_u32 + STG_F * 4,
                     kbase + (size_t)SKK * NDIM, mbase + (size_t)SKK * NDIM,
                     wid, lane);
    cp_commit();

    unsigned long long accA[R / 2];   // col n0,   row pairs packed
    unsigned long long accB[R / 2];   // col n0+1
    #pragma unroll
    for (int j = 0; j < R / 2; ++j) { accA[j] = 0ULL; accB[j] = 0ULL; }

    const int c2 = 2 * tid;           // this thread's col pair (inside its warp's slice)

    #pragma unroll 1
    for (int st = 0; st < NKST; ++st) {
        cp_wait<1>();          // own stage-st copies complete
        __syncwarp();          // whole warp's slice copies complete & visible

        const unsigned bofs = (unsigned)((st % NSTG) * STG_F) * 4u;
        const int kk0 = st * SKK;

        #pragma unroll
        for (int j = 0; j < SKK; ++j) {
            unsigned long long kraw, mraw;
            const unsigned a = (unsigned)((j * TNB + c2) * 4);
            asm volatile("ld.shared.b64 %0, [%1];" : "=l"(kraw) : "r"(ks_u32 + bofs + a));
            asm volatile("ld.shared.b64 %0, [%1];" : "=l"(mraw) : "r"(ms_u32 + bofs + a));
            const unsigned long long wm = mul_f32x2(kraw, mraw);
            unsigned lo, hi;
            u64_unpack(wm, lo, hi);
            const unsigned long long wA = u64_pack(lo, lo);
            const unsigned long long wB = u64_pack(hi, hi);

            const ulonglong2* xp =
                reinterpret_cast<const ulonglong2*>(xs + (kk0 + j) * RGP);
            #pragma unroll
            for (int j4 = 0; j4 < R / 4; ++j4) {
                ulonglong2 xv = xp[j4];             // LDS.128 broadcast
                accA[2 * j4]     = fma_f32x2(xv.x, wA, accA[2 * j4]);
                accB[2 * j4]     = fma_f32x2(xv.x, wB, accB[2 * j4]);
                accA[2 * j4 + 1] = fma_f32x2(xv.y, wA, accA[2 * j4 + 1]);
                accB[2 * j4 + 1] = fma_f32x2(xv.y, wB, accB[2 * j4 + 1]);
            }
        }

        // refill the buffer just consumed (warp-private: safe by program
        // order), or commit an empty group to keep the accounting advancing.
        const int nst = st + 2;
        if (nst < NKST) {
            const unsigned nofs = (unsigned)((nst % NSTG) * STG_F) * 4u;
            issue_warp_stage(ks_u32 + nofs, ms_u32 + nofs,
                             kbase + (size_t)nst * SKK * NDIM,
                             mbase + (size_t)nst * SKK * NDIM, wid, lane);
        }
        cp_commit();
    }

    // ---- scatter partials: g_partial[kz][row][n0..n0+1] ----
    #pragma unroll
    for (int j = 0; j < R / 2; ++j) {
        unsigned a0, a1, b0, b1;
        u64_unpack(accA[j], a0, a1);
        u64_unpack(accB[j], b0, b1);
        int r0 = rg + 2 * j, r1 = r0 + 1;
        if (r0 < rend) {
            float2 v = make_float2(__uint_as_float(a0), __uint_as_float(b0));
            *reinterpret_cast<float2*>(pbase + (size_t)srows[r0] * NDIM) = v;
        }
        if (r1 < rend) {
            float2 v = make_float2(__uint_as_float(a1), __uint_as_float(b1));
            *reinterpret_cast<float2*>(pbase + (size_t)srows[r1] * NDIM) = v;
        }
    }
}

// ---------------------------------------------------------------------------
// Fused kernel. grid = (NTILES, NSTATES, KSPLIT) = 640 blocks -> SINGLE WAVE
// at 5 blocks/SM. One block per (ntile, state, kz) handles ALL its rows.
// ---------------------------------------------------------------------------
__global__ void __launch_bounds__(NTHREADS, 5) mdl_fused(
    const float* __restrict__ x,
    const int*   __restrict__ state,
    const float* __restrict__ kern,
    const float* __restrict__ masks,
    float*       __restrict__ out)
{
    const int s     = blockIdx.y;
    const int ntile = blockIdx.x;
    const int kz    = blockIdx.z;
    const int tid   = threadIdx.x;

    extern __shared__ __align__(16) float dsm[];
    float* ks_buf = dsm;                        // [NSTG][SKK][TNB]
    float* ms_buf = dsm + KS_FLOATS;
    float* xs     = dsm + 2 * KS_FLOATS;        // [TKB][RGP]
    const unsigned ks_u32 = (unsigned)__cvta_generic_to_shared(ks_buf);
    const unsigned ms_u32 = (unsigned)__cvta_generic_to_shared(ms_buf);

    __shared__ int srows[BSZ];
    __shared__ int warp_cnt[8];
    __shared__ int s_ms;
    __shared__ int s_last;

    // ---- deterministic (ascending) row list via warp ballots ----
    {
        const int lane = tid & 31;
        const int w    = tid >> 5;                  // 4 warps
        const int r0   = w * 32 + lane;             // rows 0..127
        const int r1   = 128 + w * 32 + lane;       // rows 128..255
        const bool m0 = (state[r0] == s);
        const bool m1 = (state[r1] == s);
        const unsigned b0 = __ballot_sync(0xffffffffu, m0);
        const unsigned b1 = __ballot_sync(0xffffffffu, m1);
        if (lane == 0) { warp_cnt[w] = __popc(b0); warp_cnt[4 + w] = __popc(b1); }
        __syncthreads();
        int preA = 0, preB = 0, tot = 0;
        #pragma unroll
        for (int i = 0; i < 8; ++i) {
            int c = warp_cnt[i];
            if (i < w)              preA += c;
            if (i < 4 || i < 4 + w) preB += c;
            tot += c;
        }
        const unsigned ltmask = (1u << lane) - 1u;
        if (m0) srows[preA + __popc(b0 & ltmask)] = r0;
        if (m1) srows[preB + __popc(b1 & ltmask)] = r1;
        if (tid == 0) s_ms = tot;
        __syncthreads();
    }
    const int ms = s_ms;
    if (ms == 0) return;   // state absent -> no outputs, no arrivals needed

    const int kb = kz * TKB;
    const int n0 = ntile * TNB + 2 * tid;
    const float* kbase = kern  + (size_t)kb * NDIM + ntile * TNB;
    const float* mbase = masks + ((size_t)s * KDIM + kb) * NDIM + ntile * TNB;
    float*       pbase = g_partial + (size_t)kz * BSZ * NDIM + n0;

    // ---- all rows of this state, groups of <=16 (single group if ms<=16) ----
    int cs = 0;
    while (cs < ms) {
        int left = ms - cs;
        if (left <= 8) { group_body<8 >(cs, ms, tid, kb, x, kbase, mbase, srows, xs, ks_u32, ms_u32, pbase); cs += 8;  }
        else           { group_body<16>(cs, ms, tid, kb, x, kbase, mbase, srows, xs, ks_u32, ms_u32, pbase); cs += 16; }
    }
    cp_wait<0>();   // drain trailing (possibly empty) groups before exit path

    // ---- split-K completion handshake (threadFenceReduction pattern) ----
    __threadfence();
    __syncthreads();
    const int region = ntile * NSTATES + s;
    if (tid == 0) {
        unsigned old = atomicAdd(&g_arrive[region], 1u);
        s_last = (old == ARRIVALS - 1);
        if (s_last) g_arrive[region] = 0;   // reset for next graph replay
    }
    __syncthreads();
    if (!s_last) return;
    __threadfence();   // acquire side

    // ---- last block per region: reduce KSPLIT partials + ReLU ----
    for (int r = 0; r < ms; ++r) {
        const int row = srows[r];
        const float* pr = g_partial + (size_t)row * NDIM + n0;
        float2 acc = *reinterpret_cast<const float2*>(pr);
        #pragma unroll
        for (int z = 1; z < KSPLIT; ++z) {
            float2 b = *reinterpret_cast<const float2*>(pr + (size_t)z * BSZ * NDIM);
            acc.x += b.x; acc.y += b.y;
        }
        acc.x = fmaxf(acc.x, 0.f);
        acc.y = fmaxf(acc.y, 0.f);
        *reinterpret_cast<float2*>(out + (size_t)row * NDIM + n0) = acc;
    }
}

// ---------------------------------------------------------------------------
extern "C" void kernel_launch(void* const* d_in, const int* in_sizes, int n_in,
                              void* d_out, int out_size)
{
    const float* x     = nullptr;
    const int*   state = nullptr;
    const float* kern  = nullptr;
    const float* masks = nullptr;
    for (int i = 0; i < n_in; ++i) {
        switch (in_sizes[i]) {
            case BSZ * KDIM:            x     = (const float*)d_in[i]; break;
            case BSZ:                   state = (const int*)  d_in[i]; break;
            case KDIM * NDIM:           kern  = (const float*)d_in[i]; break;
            case NSTATES * KDIM * NDIM: masks = (const float*)d_in[i]; break;
            default: break;
        }
    }
    float* out = (float*)d_out;

    // dynamic smem opt-in (host-side attribute set; not an allocation)
    cudaFuncSetAttribute(mdl_fused, cudaFuncAttributeMaxDynamicSharedMemorySize,
                         SMEM_BYTES);

    dim3 grid(NTILES, NSTATES, KSPLIT);
    mdl_fused<<<grid, NTHREADS, SMEM_BYTES>>>(x, state, kern, masks, out);
}